// round 16
// baseline (speedup 1.0000x reference)
#include <cuda_runtime.h>
#include <cuda_bf16.h>

#define B   32
#define U   32
#define TK  64
#define TDEC 64
#define D   512
#define V   50257
#define NVBLK 393     // (V+127)/128
#define USPLIT 8      // k_main handles u<USPLIT; k_tatt_far handles the rest

// ---------------- scratch ----------------
__device__ float g_local_dec[B*D];
__device__ float g_dec_ua[B*D];
__device__ float g_dec_ta[B*D];
__device__ float g_target_out[B*D];
__device__ int   g_sel[B];
__device__ float g_logits[(long)B*V];
__device__ float g_m[B];
__device__ float g_inv_s[B];
__device__ unsigned g_hhi[B*256];
__device__ unsigned g_hlo[B*256];
__device__ uint4 g_hp[B*128];
__device__ float g_pm[B*512];
__device__ float g_ps[B*512];

// ---------------- helpers ----------------
__device__ __forceinline__ float ftanh(float x){
    float y; asm("tanh.approx.f32 %0, %1;" : "=f"(y) : "f"(x)); return y;
}
__device__ __forceinline__ float wsum(float v){
    #pragma unroll
    for (int o=16;o;o>>=1) v += __shfl_xor_sync(0xffffffffu, v, o);
    return v;
}
__device__ __forceinline__ float wmax(float v){
    #pragma unroll
    for (int o=16;o;o>>=1) v = fmaxf(v, __shfl_xor_sync(0xffffffffu, v, o));
    return v;
}
__device__ __forceinline__ unsigned smem_u32(const void* p){
    unsigned a;
    asm("{ .reg .u64 t; cvta.to.shared.u64 t, %1; cvt.u32.u64 %0, t; }" : "=r"(a) : "l"(p));
    return a;
}

// cp.async
#define CPA(dst, src) asm volatile("cp.async.cg.shared.global [%0], [%1], 16;" :: "r"(dst), "l"(src) : "memory")
#define CPC()  asm volatile("cp.async.commit_group;" ::: "memory")
#define CPW3() asm volatile("cp.async.wait_group 3;" ::: "memory")

// bf16 mma m16n8k16
__device__ __forceinline__ void mma16816(float* d, unsigned a0, unsigned a1,
                                         unsigned a2, unsigned a3,
                                         unsigned b0, unsigned b1){
    asm volatile("mma.sync.aligned.m16n8k16.row.col.f32.bf16.bf16.f32 "
        "{%0,%1,%2,%3}, {%4,%5,%6,%7}, {%8,%9}, {%0,%1,%2,%3};"
        : "+f"(d[0]), "+f"(d[1]), "+f"(d[2]), "+f"(d[3])
        : "r"(a0), "r"(a1), "r"(a2), "r"(a3), "r"(b0), "r"(b1));
}
__device__ __forceinline__ void cvt_hilo(float2 f, unsigned &hi, unsigned &lo){
    __nv_bfloat162 h = __float22bfloat162_rn(f);
    float2 fh = __bfloat1622float2(h);
    __nv_bfloat162 l = __float22bfloat162_rn(make_float2(f.x - fh.x, f.y - fh.y));
    hi = *(unsigned*)&h; lo = *(unsigned*)&l;
}

// ---------------- K1: layernorm ----------------
__global__ void k_ln(const float* __restrict__ tf, const float* __restrict__ g,
                     const float* __restrict__ bb){
    int b = blockIdx.x, tid = threadIdx.x;
    const float* row = tf + (b*TDEC + (TDEC-1))*D;
    float x0 = row[tid], x1 = row[tid+256];
    __shared__ float s1[256], s2[256];
    s1[tid] = x0+x1; s2[tid] = x0*x0 + x1*x1;
    __syncthreads();
    for (int o=128;o;o>>=1){
        if (tid<o){ s1[tid]+=s1[tid+o]; s2[tid]+=s2[tid+o]; }
        __syncthreads();
    }
    float mu = s1[0]*(1.0f/D);
    float var = s2[0]*(1.0f/D) - mu*mu;
    float r = rsqrtf(var + 1e-5f);
    g_local_dec[b*D+tid]     = (x0-mu)*r*g[tid]     + bb[tid];
    g_local_dec[b*D+tid+256] = (x1-mu)*r*g[tid+256] + bb[tid+256];
}

// ---------------- K2: dec projections ----------------
__global__ void k_proj(const float* __restrict__ ua_Wp, const float* __restrict__ ua_bp,
                       const float* __restrict__ ta_Wp, const float* __restrict__ ta_bp){
    int which = blockIdx.z;
    const float* W    = which ? ta_Wp : ua_Wp;
    const float* bias = which ? ta_bp : ua_bp;
    float* outp       = which ? g_dec_ta : g_dec_ua;
    int warp = threadIdx.x >> 5, lane = threadIdx.x & 31;
    int d = blockIdx.x*8 + warp;
    const float4* wrow = (const float4*)(W + (long)d*D);
    float4 w4[4];
    #pragma unroll
    for (int i=0;i<4;i++) w4[i] = wrow[i*32 + lane];
    float bval = bias[d];
    #pragma unroll
    for (int bi=0; bi<8; bi++){
        int b = blockIdx.y*8 + bi;
        const float4* t = (const float4*)(g_local_dec + b*D);
        float acc = 0.f;
        #pragma unroll
        for (int i=0;i<4;i++){
            float4 t4 = t[i*32 + lane];
            acc += w4[i].x*t4.x + w4[i].y*t4.y + w4[i].z*t4.z + w4[i].w*t4.w;
        }
        acc = wsum(acc);
        if (!lane) outp[b*D + d] = acc + bval;
    }
}

// ---------------- K3: utterance attention + argmax + p_gen ----------------
__global__ void k_uatt(const float* __restrict__ enc, const float* __restrict__ umask,
                       const float* __restrict__ cov, const float* __restrict__ ua_wc,
                       const float* __restrict__ ua_v, const float* __restrict__ pgen_W,
                       const float* __restrict__ pgen_b,
                       float* __restrict__ o_ucov, float* __restrict__ o_pgen,
                       float* __restrict__ o_uidx){
    int b = blockIdx.x, tid = threadIdx.x;
    int warp = tid>>5, lane = tid&31;
    __shared__ float s_scores[U], s_attn[U], s_red[256];
    float4 dec4[4], wc4[4], v4[4];
    #pragma unroll
    for (int i=0;i<4;i++){
        int d = i*128 + lane*4;
        dec4[i] = *(const float4*)(g_dec_ua + b*D + d);
        wc4[i]  = *(const float4*)(ua_wc + d);
        v4[i]   = *(const float4*)(ua_v + d);
    }
    #pragma unroll
    for (int uu=0; uu<4; uu++){
        int u = warp + uu*8;
        float c = cov[b*U + u];
        const float4* e = (const float4*)(enc + (long)(b*U + u)*D);
        float acc = 0.f;
        #pragma unroll
        for (int i=0;i<4;i++){
            float4 x = e[i*32 + lane];
            acc += ftanh(x.x + dec4[i].x + c*wc4[i].x) * v4[i].x;
            acc += ftanh(x.y + dec4[i].y + c*wc4[i].y) * v4[i].y;
            acc += ftanh(x.z + dec4[i].z + c*wc4[i].z) * v4[i].z;
            acc += ftanh(x.w + dec4[i].w + c*wc4[i].w) * v4[i].w;
        }
        acc = wsum(acc);
        if (!lane) s_scores[u] = acc;
    }
    __syncthreads();
    if (warp == 0){
        int u = lane;
        float s = s_scores[u];
        float m = wmax(s);
        float e = expf(s - m);
        float den = wsum(e);
        float a_ = (e/den) * umask[b*U+u];
        float nf = wsum(a_);
        float attn = a_ / (nf == 0.f ? 1.f : nf);
        s_attn[u] = attn;
        o_ucov[b*U+u] = cov[b*U+u] + attn;
        float bv = attn; int bi = u;
        #pragma unroll
        for (int o=16;o;o>>=1){
            float ov = __shfl_xor_sync(0xffffffffu, bv, o);
            int   oi = __shfl_xor_sync(0xffffffffu, bi, o);
            if (ov > bv || (ov == bv && oi < bi)){ bv = ov; bi = oi; }
        }
        if (!lane){ g_sel[b] = bi; o_uidx[b] = (float)bi; }
    }
    __syncthreads();
    float part = 0.f;
    #pragma unroll
    for (int j=0;j<2;j++){
        int d = tid + j*256;
        float acc = 0.f;
        #pragma unroll 8
        for (int u=0;u<U;u++) acc += s_attn[u] * enc[(long)(b*U+u)*D + d];
        part += pgen_W[d]*acc + pgen_W[D + d]*g_local_dec[b*D + d];
    }
    s_red[tid] = part;
    __syncthreads();
    for (int o=128;o;o>>=1){ if (tid<o) s_red[tid]+=s_red[tid+o]; __syncthreads(); }
    if (!tid) o_pgen[b] = 1.f/(1.f + expf(-(s_red[0] + pgen_b[0])));
}

// ---------------- shared device body: token attention for one (u,b) tile ------
__device__ __forceinline__ void tatt_tile(
    const float* __restrict__ tok, const float* __restrict__ tmask,
    const float* __restrict__ tcov, const float* __restrict__ ta_wc,
    const float* __restrict__ ta_v, float* __restrict__ o_ntc,
    float* __restrict__ o_tattn, float* ring,
    float* s_scores, float* s_attn, float* s_cov,
    int u, int b, bool is_sel)
{
    int tid = threadIdx.x, warp = tid>>5, lane = tid&31;
    int ub = u*B + b;
    float* wring = ring + warp*2048;
    unsigned rb = smem_u32(wring);
    const float* rowbase = tok + (long)ub*TK*D;
    if (tid < TK) s_cov[tid] = tcov[ub*TK + tid];

    float4 dec4[4], wc4[4], v4[4];
    #pragma unroll
    for (int i=0;i<4;i++){
        int d = i*128 + lane*4;
        dec4[i] = *(const float4*)(g_dec_ta + b*D + d);
        wc4[i]  = *(const float4*)(ta_wc + d);
        v4[i]   = *(const float4*)(ta_v + d);
    }
    #pragma unroll
    for (int s=0;s<3;s++){
        const float* src = rowbase + (warp*8+s)*D;
        #pragma unroll
        for (int i=0;i<4;i++)
            CPA(rb + (unsigned)(s*512 + (i*32+lane)*4)*4u, src + (i*32+lane)*4);
        CPC();
    }
    __syncthreads();   // s_cov ready
    #pragma unroll
    for (int tt=0; tt<8; tt++){
        if (tt < 5){
            const float* src = rowbase + (warp*8+tt+3)*D;
            int s = (tt+3)&3;
            #pragma unroll
            for (int i=0;i<4;i++)
                CPA(rb + (unsigned)(s*512 + (i*32+lane)*4)*4u, src + (i*32+lane)*4);
        }
        CPC();
        CPW3();
        float c = s_cov[warp*8+tt];
        const float4* xs = (const float4*)(wring + (tt&3)*512);
        float acc = 0.f;
        #pragma unroll
        for (int i=0;i<4;i++){
            float4 x = xs[i*32+lane];
            acc += ftanh(x.x + dec4[i].x + c*wc4[i].x)*v4[i].x;
            acc += ftanh(x.y + dec4[i].y + c*wc4[i].y)*v4[i].y;
            acc += ftanh(x.z + dec4[i].z + c*wc4[i].z)*v4[i].z;
            acc += ftanh(x.w + dec4[i].w + c*wc4[i].w)*v4[i].w;
        }
        acc = wsum(acc);
        if (!lane) s_scores[warp*8+tt] = acc;
    }
    __syncthreads();
    if (warp == 0){
        float s0 = s_scores[lane], s1 = s_scores[lane+32];
        float m = wmax(fmaxf(s0,s1));
        float e0 = expf(s0-m), e1 = expf(s1-m);
        float den = wsum(e0+e1);
        float a0 = (e0/den)*tmask[ub*TK+lane];
        float a1 = (e1/den)*tmask[ub*TK+lane+32];
        float nf = wsum(a0+a1);
        float inv = 1.f/((nf==0.f)?1.f:nf);
        a0 *= inv; a1 *= inv;
        s_attn[lane] = a0; s_attn[lane+32] = a1;
        o_ntc[ub*TK+lane]    = s_cov[lane]    + a0;
        o_ntc[ub*TK+lane+32] = s_cov[lane+32] + a1;
        if (is_sel){ o_tattn[b*TK+lane] = a0; o_tattn[b*TK+lane+32] = a1; }
    }
    __syncthreads();
    if (is_sel){
        #pragma unroll
        for (int j=0;j<2;j++){
            int d = tid + j*256;
            float acc = 0.f;
            #pragma unroll 8
            for (int t=0;t<TK;t++) acc += s_attn[t]*tok[(long)ub*TK*D + t*D + d];
            g_target_out[b*D + d] = acc;
        }
    }
}

// ---------------- K4a: selected-tile token attention (32 blocks) -------------
__global__ void __launch_bounds__(256,3)
k_tatt_sel(const float* __restrict__ tok, const float* __restrict__ tmask,
           const float* __restrict__ tcov, const float* __restrict__ ta_wc,
           const float* __restrict__ ta_v,
           float* __restrict__ o_ntc, float* __restrict__ o_tattn){
    extern __shared__ float ring[];
    __shared__ float s_scores[TK], s_attn[TK], s_cov[TK];
    int b = blockIdx.x;
    int u = g_sel[b];
    tatt_tile(tok, tmask, tcov, ta_wc, ta_v, o_ntc, o_tattn,
              ring, s_scores, s_attn, s_cov, u, b, true);
}

// ---------------- K4b: far token tiles (u >= USPLIT), runs on stream 2 -------
__global__ void __launch_bounds__(256,3)
k_tatt_far(const float* __restrict__ tok, const float* __restrict__ tmask,
           const float* __restrict__ tcov, const float* __restrict__ ta_wc,
           const float* __restrict__ ta_v,
           float* __restrict__ o_ntc, float* __restrict__ o_tattn){
    extern __shared__ float ring[];
    __shared__ float s_scores[TK], s_attn[TK], s_cov[TK];
    int u = USPLIT + (blockIdx.x >> 5), b = blockIdx.x & 31;
    if (u == g_sel[b]) return;
    tatt_tile(tok, tmask, tcov, ta_wc, ta_v, o_ntc, o_tattn,
              ring, s_scores, s_attn, s_cov, u, b, false);
}

// ---------------- K5: h -> bf16 hi/lo ----------------
__global__ void k_h(const float* __restrict__ W1, const float* __restrict__ b1){
    int warp = threadIdx.x>>5, lane = threadIdx.x&31;
    int d = blockIdx.x*8 + warp;
    const float4* w = (const float4*)(W1 + (long)d*2*D);
    float4 w4[8];
    #pragma unroll
    for (int i=0;i<8;i++) w4[i] = w[i*32+lane];
    float bval = b1[d];
    #pragma unroll
    for (int bi=0; bi<8; bi++){
        int b = blockIdx.y*8 + bi;
        const float4* t0 = (const float4*)(g_target_out + b*D);
        const float4* t1 = (const float4*)(g_local_dec + b*D);
        float acc=0.f;
        #pragma unroll
        for (int i=0;i<4;i++){
            float4 x = t0[i*32+lane];
            acc += w4[i].x*x.x + w4[i].y*x.y + w4[i].z*x.z + w4[i].w*x.w;
        }
        #pragma unroll
        for (int i=0;i<4;i++){
            float4 x = t1[i*32+lane];
            acc += w4[i+4].x*x.x + w4[i+4].y*x.y + w4[i+4].z*x.z + w4[i+4].w*x.w;
        }
        acc = wsum(acc);
        if (!lane){
            float h = acc + bval;
            __nv_bfloat16 hi = __float2bfloat16(h);
            __nv_bfloat16 lo = __float2bfloat16(h - __bfloat162float(hi));
            ((__nv_bfloat16*)g_hhi)[b*512 + d] = hi;
            ((__nv_bfloat16*)g_hlo)[b*512 + d] = lo;
        }
    }
}

// ---------------- K5b: pack B fragments as uint4 pairs ----------------
__global__ void k_pack(){
    int i = blockIdx.x*256 + threadIdx.x;      // 0..4095
    int n = i >> 7, j = i & 127;
    int kc = j >> 2, tg = j & 3;
    int kp = n*256 + kc*8 + tg;
    g_hp[i] = make_uint4(g_hhi[kp], g_hlo[kp], g_hhi[kp+4], g_hlo[kp+4]);
}

// ---------------- K6: FUSED vocab GEMM + near token tiles (u < USPLIT) -------
#define WNST 5
#define WSTGF 256
#define MAIN_SMEM 65536
__global__ void __launch_bounds__(256,3)
k_main(const float* __restrict__ W2, const float* __restrict__ b2,
       const float* __restrict__ tok, const float* __restrict__ tmask,
       const float* __restrict__ tcov, const float* __restrict__ ta_wc,
       const float* __restrict__ ta_v,
       float* __restrict__ o_ntc, float* __restrict__ o_tattn){
    extern __shared__ char smraw[];
    __shared__ float sm_m[8][32], sm_s[8][32];
    __shared__ float s_scores[TK], s_attn[TK], s_cov[TK];
    int tid = threadIdx.x, wm = tid>>5, lane = tid&31;

    if (blockIdx.x >= NVBLK){
        int idx = blockIdx.x - NVBLK;
        int u = idx >> 5, b = idx & 31;
        if (u == g_sel[b]) return;   // done by k_tatt_sel
        tatt_tile(tok, tmask, tcov, ta_wc, ta_v, o_ntc, o_tattn,
                  (float*)smraw, s_scores, s_attn, s_cov, u, b, false);
        return;
    }

    // ------- vocab GEMM path -------
    float* sW = (float*)smraw;
    int g = lane>>2, tg = lane&3;
    long v0 = (long)blockIdx.x * 128;

    int idx0 = lane*2, idx1 = lane*2+1;
    int row0 = idx0>>2, c40 = idx0&3;
    int row1 = idx1>>2, c41 = idx1&3;
    long gv0 = v0 + wm*16 + row0; if (gv0 >= V) gv0 = V-1;
    long gv1 = v0 + wm*16 + row1; if (gv1 >= V) gv1 = V-1;
    const float* src0 = W2 + gv0*D + c40*4;
    const float* src1 = W2 + gv1*D + c41*4;
    float* wbase = sW + wm*WNST*WSTGF;
    unsigned sb = smem_u32(wbase);
    unsigned dst0 = sb + (unsigned)(row0*64 + ((c40 ^ (row0&3))*16));
    unsigned dst1 = sb + (unsigned)(row1*64 + ((c41 ^ (row1&3))*16));

    #pragma unroll
    for (int s=0; s<4; s++){
        CPA(dst0 + (unsigned)s*1024u, src0 + s*16);
        CPA(dst1 + (unsigned)s*1024u, src1 + s*16);
        CPC();
    }

    float dd[4][4];
    #pragma unroll
    for (int nt=0;nt<4;nt++){ dd[nt][0]=dd[nt][1]=dd[nt][2]=dd[nt][3]=0.f; }

    int r3 = g & 3;
    int o_lo = ((tg>>1) ^ r3)*4 + (tg&1)*2;
    int o_hi = (((tg>>1)|2) ^ r3)*4 + (tg&1)*2;
    int rA = g*16, rB = (g+8)*16;
    const uint4* hp = g_hp + (long)g*128 + tg;

    for (int kc=0; kc<32; kc++){
        CPW3();
        if (kc+4 < 32){
            unsigned st = (unsigned)((kc+4)%WNST)*1024u;
            CPA(dst0 + st, src0 + (kc+4)*16);
            CPA(dst1 + st, src1 + (kc+4)*16);
        }
        CPC();

        const float* sw = wbase + (kc%WNST)*WSTGF;
        float2 fa0 = *(const float2*)(sw + rA + o_lo);
        float2 fa1 = *(const float2*)(sw + rB + o_lo);
        float2 fa2 = *(const float2*)(sw + rA + o_hi);
        float2 fa3 = *(const float2*)(sw + rB + o_hi);

        unsigned ah0,al0,ah1,al1,ah2,al2,ah3,al3;
        cvt_hilo(fa0, ah0, al0);
        cvt_hilo(fa1, ah1, al1);
        cvt_hilo(fa2, ah2, al2);
        cvt_hilo(fa3, ah3, al3);

        const uint4* hpk = hp + kc*4;
        #pragma unroll
        for (int nt=0; nt<4; nt++){
            uint4 bc = hpk[(long)nt*1024];
            mma16816(dd[nt], ah0, ah1, ah2, ah3, bc.x, bc.z);  // hi*hi
            mma16816(dd[nt], al0, al1, al2, al3, bc.x, bc.z);  // lo*hi
            mma16816(dd[nt], ah0, ah1, ah2, ah3, bc.y, bc.w);  // hi*lo
        }
    }

    long rr0 = v0 + wm*16 + g;
    long rr1 = rr0 + 8;
    bool ok0 = (rr0 < V), ok1 = (rr1 < V);
    float bias0 = ok0 ? b2[rr0] : 0.f;
    float bias1 = ok1 ? b2[rr1] : 0.f;
    #pragma unroll
    for (int nt=0; nt<4; nt++){
        int n = nt*8 + tg*2;
        if (ok0){
            g_logits[(long)n*V + rr0]     = dd[nt][0] + bias0;
            g_logits[(long)(n+1)*V + rr0] = dd[nt][1] + bias0;
        }
        if (ok1){
            g_logits[(long)n*V + rr1]     = dd[nt][2] + bias1;
            g_logits[(long)(n+1)*V + rr1] = dd[nt][3] + bias1;
        }
    }

    // fused partial softmax stats
    #pragma unroll
    for (int nt=0; nt<4; nt++){
        #pragma unroll
        for (int p=0; p<2; p++){
            float x0 = ok0 ? dd[nt][p]   + bias0 : -1e30f;
            float x1 = ok1 ? dd[nt][p+2] + bias1 : -1e30f;
            float m = fmaxf(x0, x1);
            #pragma unroll
            for (int o=4; o<32; o<<=1) m = fmaxf(m, __shfl_xor_sync(0xffffffffu, m, o));
            float s = (ok0 ? expf(x0 - m) : 0.f) + (ok1 ? expf(x1 - m) : 0.f);
            #pragma unroll
            for (int o=4; o<32; o<<=1) s += __shfl_xor_sync(0xffffffffu, s, o);
            if (g == 0){
                int n = nt*8 + tg*2 + p;
                sm_m[wm][n] = m;
                sm_s[wm][n] = s;
            }
        }
    }
    __syncthreads();
    if (wm == 0){
        float M = -1e30f;
        #pragma unroll
        for (int w=0; w<8; w++) M = fmaxf(M, sm_m[w][lane]);
        float S = 0.f;
        #pragma unroll
        for (int w=0; w<8; w++) S += sm_s[w][lane] * expf(sm_m[w][lane] - M);
        g_pm[(long)lane*512 + blockIdx.x] = M;
        g_ps[(long)lane*512 + blockIdx.x] = S;
    }
}

// ---------------- K7: combine partial stats (tiny) ----------------
__global__ void k_red(){
    int b = blockIdx.x, tid = threadIdx.x;
    __shared__ float smm[256], sms[256];
    float m0 = (tid      < NVBLK) ? g_pm[(long)b*512 + tid]       : -1e30f;
    float s0 = (tid      < NVBLK) ? g_ps[(long)b*512 + tid]       : 0.f;
    float m1 = (tid+256  < NVBLK) ? g_pm[(long)b*512 + tid + 256] : -1e30f;
    float s1 = (tid+256  < NVBLK) ? g_ps[(long)b*512 + tid + 256] : 0.f;
    float m = fmaxf(m0, m1);
    smm[tid] = m;
    __syncthreads();
    for (int o=128;o;o>>=1){ if (tid<o) smm[tid]=fmaxf(smm[tid],smm[tid+o]); __syncthreads(); }
    float M = smm[0];
    __syncthreads();
    float s = s0*expf(m0 - M) + s1*expf(m1 - M);
    sms[tid] = s;
    __syncthreads();
    for (int o=128;o;o>>=1){ if (tid<o) sms[tid]+=sms[tid+o]; __syncthreads(); }
    if (!tid){ g_m[b] = M; g_inv_s[b] = 1.f/sms[0]; }
}

// ---------------- K8: vocab_dist ----------------
__global__ void k_soft(float* __restrict__ o_vocab){
    long i = (long)blockIdx.x*256 + threadIdx.x;
    if (i >= (long)B*V) return;
    int b = (int)(i / V);
    o_vocab[i] = expf(g_logits[i] - g_m[b]) * g_inv_s[b];
}

// ---------------- launch ----------------
extern "C" void kernel_launch(void* const* d_in, const int* in_sizes, int n_in,
                              void* d_out, int out_size){
    const float* tf    = (const float*)d_in[0];
    const float* enc   = (const float*)d_in[2];
    const float* umask = (const float*)d_in[3];
    const float* tok   = (const float*)d_in[4];
    const float* tmask = (const float*)d_in[5];
    const float* cov   = (const float*)d_in[6];
    const float* tcov  = (const float*)d_in[7];
    const float* ua_Wp = (const float*)d_in[8];
    const float* ua_bp = (const float*)d_in[9];
    const float* ua_v  = (const float*)d_in[10];
    const float* ua_wc = (const float*)d_in[11];
    const float* ta_Wp = (const float*)d_in[12];
    const float* ta_bp = (const float*)d_in[13];
    const float* ta_v  = (const float*)d_in[14];
    const float* ta_wc = (const float*)d_in[15];
    const float* pgen_W= (const float*)d_in[16];
    const float* pgen_b= (const float*)d_in[17];
    const float* W1    = (const float*)d_in[18];
    const float* b1    = (const float*)d_in[19];
    const float* W2    = (const float*)d_in[20];
    const float* b2    = (const float*)d_in[21];
    const float* ln_g  = (const float*)d_in[22];
    const float* ln_b  = (const float*)d_in[23];

    float* out = (float*)d_out;
    float* o_vocab = out;
    float* o_tattn = o_vocab + (long)B*V;
    float* o_pgen  = o_tattn + B*TK;
    float* o_ucov  = o_pgen + B;
    float* o_ntc   = o_ucov + B*U;
    float* o_uidx  = o_ntc + (long)U*B*TK;

    // lazily created once (first, non-captured correctness call); reused in graph
    static cudaStream_t s2 = nullptr;
    static cudaEvent_t evFork = nullptr, evJoin = nullptr;
    if (!s2){
        cudaStreamCreateWithFlags(&s2, cudaStreamNonBlocking);
        cudaEventCreateWithFlags(&evFork, cudaEventDisableTiming);
        cudaEventCreateWithFlags(&evJoin, cudaEventDisableTiming);
        cudaFuncSetAttribute(k_tatt_sel, cudaFuncAttributeMaxDynamicSharedMemorySize, MAIN_SMEM);
        cudaFuncSetAttribute(k_tatt_far, cudaFuncAttributeMaxDynamicSharedMemorySize, MAIN_SMEM);
        cudaFuncSetAttribute(k_main, cudaFuncAttributeMaxDynamicSharedMemorySize, MAIN_SMEM);
    }

    k_ln   <<<B, 256>>>(tf, ln_g, ln_b);
    k_proj <<<dim3(D/8, B/8, 2), 256>>>(ua_Wp, ua_bp, ta_Wp, ta_bp);
    k_uatt <<<B, 256>>>(enc, umask, cov, ua_wc, ua_v, pgen_W, pgen_b,
                        o_ucov, o_pgen, o_uidx);

    // fork: far token tiles run concurrently on s2
    cudaEventRecord(evFork, 0);
    cudaStreamWaitEvent(s2, evFork, 0);
    k_tatt_far <<<(U-USPLIT)*B, 256, MAIN_SMEM, s2>>>(tok, tmask, tcov, ta_wc, ta_v,
                                                      o_ntc, o_tattn);
    cudaEventRecord(evJoin, s2);

    // stream 0: critical-path prefix, then fused main
    k_tatt_sel <<<B, 256, MAIN_SMEM>>>(tok, tmask, tcov, ta_wc, ta_v, o_ntc, o_tattn);
    k_h    <<<dim3(D/8, B/8), 256>>>(W1, b1);
    k_pack <<<16, 256>>>();
    k_main <<<NVBLK + USPLIT*B, 256, MAIN_SMEM>>>(W2, b2, tok, tmask, tcov, ta_wc, ta_v,
                                                  o_ntc, o_tattn);
    // join s2 before the epilogue
    cudaStreamWaitEvent(0, evJoin, 0);
    k_red  <<<B, 256>>>();
    k_soft <<<(int)(((long)B*V + 255)/256), 256>>>(o_vocab);
}

// round 17
// speedup vs baseline: 1.0711x; 1.0711x over previous
#include <cuda_runtime.h>
#include <cuda_bf16.h>

#define B   32
#define U   32
#define TK  64
#define TDEC 64
#define D   512
#define V   50257
#define NVBLK 393     // (V+127)/128

// ---------------- scratch ----------------
__device__ float g_local_dec[B*D];
__device__ float g_dec_ua[B*D];
__device__ float g_dec_ta[B*D];
__device__ float g_target_out[B*D];
__device__ int   g_sel[B];
__device__ float g_logits[(long)B*V];
__device__ float g_m[B];
__device__ float g_inv_s[B];
__device__ unsigned g_hhi[B*256];
__device__ unsigned g_hlo[B*256];
__device__ uint4 g_hp[B*128];
__device__ float g_pm[B*512];
__device__ float g_ps[B*512];

// ---------------- helpers ----------------
__device__ __forceinline__ float ftanh(float x){
    float y; asm("tanh.approx.f32 %0, %1;" : "=f"(y) : "f"(x)); return y;
}
__device__ __forceinline__ float wsum(float v){
    #pragma unroll
    for (int o=16;o;o>>=1) v += __shfl_xor_sync(0xffffffffu, v, o);
    return v;
}
__device__ __forceinline__ float wmax(float v){
    #pragma unroll
    for (int o=16;o;o>>=1) v = fmaxf(v, __shfl_xor_sync(0xffffffffu, v, o));
    return v;
}
__device__ __forceinline__ unsigned smem_u32(const void* p){
    unsigned a;
    asm("{ .reg .u64 t; cvta.to.shared.u64 t, %1; cvt.u32.u64 %0, t; }" : "=r"(a) : "l"(p));
    return a;
}

// cp.async
#define CPA(dst, src) asm volatile("cp.async.cg.shared.global [%0], [%1], 16;" :: "r"(dst), "l"(src) : "memory")
#define CPC()  asm volatile("cp.async.commit_group;" ::: "memory")
#define CPW3() asm volatile("cp.async.wait_group 3;" ::: "memory")
#define CPW0() asm volatile("cp.async.wait_group 0;" ::: "memory")

// bf16 mma m16n8k16
__device__ __forceinline__ void mma16816(float* d, unsigned a0, unsigned a1,
                                         unsigned a2, unsigned a3,
                                         unsigned b0, unsigned b1){
    asm volatile("mma.sync.aligned.m16n8k16.row.col.f32.bf16.bf16.f32 "
        "{%0,%1,%2,%3}, {%4,%5,%6,%7}, {%8,%9}, {%0,%1,%2,%3};"
        : "+f"(d[0]), "+f"(d[1]), "+f"(d[2]), "+f"(d[3])
        : "r"(a0), "r"(a1), "r"(a2), "r"(a3), "r"(b0), "r"(b1));
}
__device__ __forceinline__ void cvt_hilo(float2 f, unsigned &hi, unsigned &lo){
    __nv_bfloat162 h = __float22bfloat162_rn(f);
    float2 fh = __bfloat1622float2(h);
    __nv_bfloat162 l = __float22bfloat162_rn(make_float2(f.x - fh.x, f.y - fh.y));
    hi = *(unsigned*)&h; lo = *(unsigned*)&l;
}

// ---------------- K1: layernorm ----------------
__global__ void k_ln(const float* __restrict__ tf, const float* __restrict__ g,
                     const float* __restrict__ bb){
    int b = blockIdx.x, tid = threadIdx.x;
    const float* row = tf + (b*TDEC + (TDEC-1))*D;
    float x0 = row[tid], x1 = row[tid+256];
    __shared__ float s1[256], s2[256];
    s1[tid] = x0+x1; s2[tid] = x0*x0 + x1*x1;
    __syncthreads();
    for (int o=128;o;o>>=1){
        if (tid<o){ s1[tid]+=s1[tid+o]; s2[tid]+=s2[tid+o]; }
        __syncthreads();
    }
    float mu = s1[0]*(1.0f/D);
    float var = s2[0]*(1.0f/D) - mu*mu;
    float r = rsqrtf(var + 1e-5f);
    g_local_dec[b*D+tid]     = (x0-mu)*r*g[tid]     + bb[tid];
    g_local_dec[b*D+tid+256] = (x1-mu)*r*g[tid+256] + bb[tid+256];
}

// ---------------- K2: dec projections ----------------
__global__ void k_proj(const float* __restrict__ ua_Wp, const float* __restrict__ ua_bp,
                       const float* __restrict__ ta_Wp, const float* __restrict__ ta_bp){
    int which = blockIdx.z;
    const float* W    = which ? ta_Wp : ua_Wp;
    const float* bias = which ? ta_bp : ua_bp;
    float* outp       = which ? g_dec_ta : g_dec_ua;
    int warp = threadIdx.x >> 5, lane = threadIdx.x & 31;
    int d = blockIdx.x*8 + warp;
    const float4* wrow = (const float4*)(W + (long)d*D);
    float4 w4[4];
    #pragma unroll
    for (int i=0;i<4;i++) w4[i] = wrow[i*32 + lane];
    float bval = bias[d];
    #pragma unroll
    for (int bi=0; bi<8; bi++){
        int b = blockIdx.y*8 + bi;
        const float4* t = (const float4*)(g_local_dec + b*D);
        float acc = 0.f;
        #pragma unroll
        for (int i=0;i<4;i++){
            float4 t4 = t[i*32 + lane];
            acc += w4[i].x*t4.x + w4[i].y*t4.y + w4[i].z*t4.z + w4[i].w*t4.w;
        }
        acc = wsum(acc);
        if (!lane) outp[b*D + d] = acc + bval;
    }
}

// ---------------- K3: utterance attention + argmax + p_gen ----------------
__global__ void k_uatt(const float* __restrict__ enc, const float* __restrict__ umask,
                       const float* __restrict__ cov, const float* __restrict__ ua_wc,
                       const float* __restrict__ ua_v, const float* __restrict__ pgen_W,
                       const float* __restrict__ pgen_b,
                       float* __restrict__ o_ucov, float* __restrict__ o_pgen,
                       float* __restrict__ o_uidx){
    int b = blockIdx.x, tid = threadIdx.x;
    int warp = tid>>5, lane = tid&31;
    __shared__ float s_scores[U], s_attn[U], s_red[256];
    float4 dec4[4], wc4[4], v4[4];
    #pragma unroll
    for (int i=0;i<4;i++){
        int d = i*128 + lane*4;
        dec4[i] = *(const float4*)(g_dec_ua + b*D + d);
        wc4[i]  = *(const float4*)(ua_wc + d);
        v4[i]   = *(const float4*)(ua_v + d);
    }
    #pragma unroll
    for (int uu=0; uu<4; uu++){
        int u = warp + uu*8;
        float c = cov[b*U + u];
        const float4* e = (const float4*)(enc + (long)(b*U + u)*D);
        float acc = 0.f;
        #pragma unroll
        for (int i=0;i<4;i++){
            float4 x = e[i*32 + lane];
            acc += ftanh(x.x + dec4[i].x + c*wc4[i].x) * v4[i].x;
            acc += ftanh(x.y + dec4[i].y + c*wc4[i].y) * v4[i].y;
            acc += ftanh(x.z + dec4[i].z + c*wc4[i].z) * v4[i].z;
            acc += ftanh(x.w + dec4[i].w + c*wc4[i].w) * v4[i].w;
        }
        acc = wsum(acc);
        if (!lane) s_scores[u] = acc;
    }
    __syncthreads();
    if (warp == 0){
        int u = lane;
        float s = s_scores[u];
        float m = wmax(s);
        float e = expf(s - m);
        float den = wsum(e);
        float a_ = (e/den) * umask[b*U+u];
        float nf = wsum(a_);
        float attn = a_ / (nf == 0.f ? 1.f : nf);
        s_attn[u] = attn;
        o_ucov[b*U+u] = cov[b*U+u] + attn;
        float bv = attn; int bi = u;
        #pragma unroll
        for (int o=16;o;o>>=1){
            float ov = __shfl_xor_sync(0xffffffffu, bv, o);
            int   oi = __shfl_xor_sync(0xffffffffu, bi, o);
            if (ov > bv || (ov == bv && oi < bi)){ bv = ov; bi = oi; }
        }
        if (!lane){ g_sel[b] = bi; o_uidx[b] = (float)bi; }
    }
    __syncthreads();
    float part = 0.f;
    #pragma unroll
    for (int j=0;j<2;j++){
        int d = tid + j*256;
        float acc = 0.f;
        #pragma unroll 8
        for (int u=0;u<U;u++) acc += s_attn[u] * enc[(long)(b*U+u)*D + d];
        part += pgen_W[d]*acc + pgen_W[D + d]*g_local_dec[b*D + d];
    }
    s_red[tid] = part;
    __syncthreads();
    for (int o=128;o;o>>=1){ if (tid<o) s_red[tid]+=s_red[tid+o]; __syncthreads(); }
    if (!tid) o_pgen[b] = 1.f/(1.f + expf(-(s_red[0] + pgen_b[0])));
}

// ---------------- shared device body: token attention for one (u,b) tile ------
// (4-stage version used inside k_main; occupancy 3)
__device__ __forceinline__ void tatt_tile(
    const float* __restrict__ tok, const float* __restrict__ tmask,
    const float* __restrict__ tcov, const float* __restrict__ ta_wc,
    const float* __restrict__ ta_v, float* __restrict__ o_ntc,
    float* __restrict__ o_tattn, float* ring,
    float* s_scores, float* s_attn, float* s_cov,
    int u, int b, bool is_sel)
{
    int tid = threadIdx.x, warp = tid>>5, lane = tid&31;
    int ub = u*B + b;
    float* wring = ring + warp*2048;
    unsigned rb = smem_u32(wring);
    const float* rowbase = tok + (long)ub*TK*D;
    if (tid < TK) s_cov[tid] = tcov[ub*TK + tid];

    float4 dec4[4], wc4[4], v4[4];
    #pragma unroll
    for (int i=0;i<4;i++){
        int d = i*128 + lane*4;
        dec4[i] = *(const float4*)(g_dec_ta + b*D + d);
        wc4[i]  = *(const float4*)(ta_wc + d);
        v4[i]   = *(const float4*)(ta_v + d);
    }
    #pragma unroll
    for (int s=0;s<3;s++){
        const float* src = rowbase + (warp*8+s)*D;
        #pragma unroll
        for (int i=0;i<4;i++)
            CPA(rb + (unsigned)(s*512 + (i*32+lane)*4)*4u, src + (i*32+lane)*4);
        CPC();
    }
    __syncthreads();   // s_cov ready
    #pragma unroll
    for (int tt=0; tt<8; tt++){
        if (tt < 5){
            const float* src = rowbase + (warp*8+tt+3)*D;
            int s = (tt+3)&3;
            #pragma unroll
            for (int i=0;i<4;i++)
                CPA(rb + (unsigned)(s*512 + (i*32+lane)*4)*4u, src + (i*32+lane)*4);
        }
        CPC();
        CPW3();
        float c = s_cov[warp*8+tt];
        const float4* xs = (const float4*)(wring + (tt&3)*512);
        float acc = 0.f;
        #pragma unroll
        for (int i=0;i<4;i++){
            float4 x = xs[i*32+lane];
            acc += ftanh(x.x + dec4[i].x + c*wc4[i].x)*v4[i].x;
            acc += ftanh(x.y + dec4[i].y + c*wc4[i].y)*v4[i].y;
            acc += ftanh(x.z + dec4[i].z + c*wc4[i].z)*v4[i].z;
            acc += ftanh(x.w + dec4[i].w + c*wc4[i].w)*v4[i].w;
        }
        acc = wsum(acc);
        if (!lane) s_scores[warp*8+tt] = acc;
    }
    __syncthreads();
    if (warp == 0){
        float s0 = s_scores[lane], s1 = s_scores[lane+32];
        float m = wmax(fmaxf(s0,s1));
        float e0 = expf(s0-m), e1 = expf(s1-m);
        float den = wsum(e0+e1);
        float a0 = (e0/den)*tmask[ub*TK+lane];
        float a1 = (e1/den)*tmask[ub*TK+lane+32];
        float nf = wsum(a0+a1);
        float inv = 1.f/((nf==0.f)?1.f:nf);
        a0 *= inv; a1 *= inv;
        s_attn[lane] = a0; s_attn[lane+32] = a1;
        o_ntc[ub*TK+lane]    = s_cov[lane]    + a0;
        o_ntc[ub*TK+lane+32] = s_cov[lane+32] + a1;
        if (is_sel){ o_tattn[b*TK+lane] = a0; o_tattn[b*TK+lane+32] = a1; }
    }
    __syncthreads();
    if (is_sel){
        #pragma unroll
        for (int j=0;j<2;j++){
            int d = tid + j*256;
            float acc = 0.f;
            #pragma unroll 8
            for (int t=0;t<TK;t++) acc += s_attn[t]*tok[(long)ub*TK*D + t*D + d];
            g_target_out[b*D + d] = acc;
        }
    }
}

// ---------------- K4: selected-tile token attention (full-depth ring) --------
// One block per batch (32 blocks, 1/SM). Whole 64x512 tile staged in smem at
// once (128KB); weighted-sum epilogue reads SMEM ONLY (no global re-read).
#define SEL_SMEM (64*512*4 + 8*512*4)   // ring 128KB + partials 16KB = 147456
__global__ void __launch_bounds__(256)
k_tatt_sel(const float* __restrict__ tok, const float* __restrict__ tmask,
           const float* __restrict__ tcov, const float* __restrict__ ta_wc,
           const float* __restrict__ ta_v,
           float* __restrict__ o_ntc, float* __restrict__ o_tattn){
    extern __shared__ float ring[];          // row t at ring + t*512
    float* s_part = ring + 64*512;           // [8][512]
    __shared__ float s_scores[TK], s_attn[TK], s_cov[TK];
    int b = blockIdx.x;
    int u = g_sel[b];
    int ub = u*B + b;
    int tid = threadIdx.x, warp = tid>>5, lane = tid&31;
    const float* rowbase = tok + (long)ub*TK*D;
    unsigned rb = smem_u32(ring + (warp*8)*512);
    if (tid < TK) s_cov[tid] = tcov[ub*TK + tid];

    // issue ALL 8 rows per warp, one commit group
    #pragma unroll
    for (int s=0;s<8;s++){
        const float* src = rowbase + (warp*8+s)*D;
        #pragma unroll
        for (int i=0;i<4;i++)
            CPA(rb + (unsigned)(s*512 + (i*32+lane)*4)*4u, src + (i*32+lane)*4);
    }
    CPC();

    // load params while DRAM is in flight
    float4 dec4[4], wc4[4], v4[4];
    #pragma unroll
    for (int i=0;i<4;i++){
        int d = i*128 + lane*4;
        dec4[i] = *(const float4*)(g_dec_ta + b*D + d);
        wc4[i]  = *(const float4*)(ta_wc + d);
        v4[i]   = *(const float4*)(ta_v + d);
    }
    CPW0();
    __syncthreads();   // tile + s_cov resident

    #pragma unroll
    for (int tt=0; tt<8; tt++){
        float c = s_cov[warp*8+tt];
        const float4* xs = (const float4*)(ring + (warp*8+tt)*512);
        float acc = 0.f;
        #pragma unroll
        for (int i=0;i<4;i++){
            float4 x = xs[i*32+lane];
            acc += ftanh(x.x + dec4[i].x + c*wc4[i].x)*v4[i].x;
            acc += ftanh(x.y + dec4[i].y + c*wc4[i].y)*v4[i].y;
            acc += ftanh(x.z + dec4[i].z + c*wc4[i].z)*v4[i].z;
            acc += ftanh(x.w + dec4[i].w + c*wc4[i].w)*v4[i].w;
        }
        acc = wsum(acc);
        if (!lane) s_scores[warp*8+tt] = acc;
    }
    __syncthreads();
    if (warp == 0){
        float s0 = s_scores[lane], s1 = s_scores[lane+32];
        float m = wmax(fmaxf(s0,s1));
        float e0 = expf(s0-m), e1 = expf(s1-m);
        float den = wsum(e0+e1);
        float a0 = (e0/den)*tmask[ub*TK+lane];
        float a1 = (e1/den)*tmask[ub*TK+lane+32];
        float nf = wsum(a0+a1);
        float inv = 1.f/((nf==0.f)?1.f:nf);
        a0 *= inv; a1 *= inv;
        s_attn[lane] = a0; s_attn[lane+32] = a1;
        o_ntc[ub*TK+lane]    = s_cov[lane]    + a0;
        o_ntc[ub*TK+lane+32] = s_cov[lane+32] + a1;
        o_tattn[b*TK+lane] = a0; o_tattn[b*TK+lane+32] = a1;
    }
    __syncthreads();

    // weighted sum from SMEM: warp w covers t in [8w, 8w+8), partials in s_part
    #pragma unroll
    for (int i=0;i<4;i++){
        float4 acc = make_float4(0.f,0.f,0.f,0.f);
        #pragma unroll
        for (int t=0;t<8;t++){
            float a = s_attn[warp*8+t];
            float4 x = ((const float4*)(ring + (warp*8+t)*512))[i*32+lane];
            acc.x += a*x.x; acc.y += a*x.y; acc.z += a*x.z; acc.w += a*x.w;
        }
        *(float4*)&s_part[warp*512 + i*128 + lane*4] = acc;
    }
    __syncthreads();
    #pragma unroll
    for (int j=0;j<2;j++){
        int d = tid + j*256;
        float acc = 0.f;
        #pragma unroll
        for (int w=0;w<8;w++) acc += s_part[w*512 + d];
        g_target_out[b*D + d] = acc;
    }
}

// ---------------- K5: h -> bf16 hi/lo ----------------
__global__ void k_h(const float* __restrict__ W1, const float* __restrict__ b1){
    int warp = threadIdx.x>>5, lane = threadIdx.x&31;
    int d = blockIdx.x*8 + warp;
    const float4* w = (const float4*)(W1 + (long)d*2*D);
    float4 w4[8];
    #pragma unroll
    for (int i=0;i<8;i++) w4[i] = w[i*32+lane];
    float bval = b1[d];
    #pragma unroll
    for (int bi=0; bi<8; bi++){
        int b = blockIdx.y*8 + bi;
        const float4* t0 = (const float4*)(g_target_out + b*D);
        const float4* t1 = (const float4*)(g_local_dec + b*D);
        float acc=0.f;
        #pragma unroll
        for (int i=0;i<4;i++){
            float4 x = t0[i*32+lane];
            acc += w4[i].x*x.x + w4[i].y*x.y + w4[i].z*x.z + w4[i].w*x.w;
        }
        #pragma unroll
        for (int i=0;i<4;i++){
            float4 x = t1[i*32+lane];
            acc += w4[i+4].x*x.x + w4[i+4].y*x.y + w4[i+4].z*x.z + w4[i+4].w*x.w;
        }
        acc = wsum(acc);
        if (!lane){
            float h = acc + bval;
            __nv_bfloat16 hi = __float2bfloat16(h);
            __nv_bfloat16 lo = __float2bfloat16(h - __bfloat162float(hi));
            ((__nv_bfloat16*)g_hhi)[b*512 + d] = hi;
            ((__nv_bfloat16*)g_hlo)[b*512 + d] = lo;
        }
    }
}

// ---------------- K5b: pack B fragments as uint4 pairs ----------------
__global__ void k_pack(){
    int i = blockIdx.x*256 + threadIdx.x;      // 0..4095
    int n = i >> 7, j = i & 127;
    int kc = j >> 2, tg = j & 3;
    int kp = n*256 + kc*8 + tg;
    g_hp[i] = make_uint4(g_hhi[kp], g_hlo[kp], g_hhi[kp+4], g_hlo[kp+4]);
}

// ---------------- K6: FUSED vocab GEMM + remaining token attention -----------
#define WNST 5
#define WSTGF 256
#define MAIN_SMEM 65536
__global__ void __launch_bounds__(256,3)
k_main(const float* __restrict__ W2, const float* __restrict__ b2,
       const float* __restrict__ tok, const float* __restrict__ tmask,
       const float* __restrict__ tcov, const float* __restrict__ ta_wc,
       const float* __restrict__ ta_v,
       float* __restrict__ o_ntc, float* __restrict__ o_tattn){
    extern __shared__ char smraw[];
    __shared__ float sm_m[8][32], sm_s[8][32];
    __shared__ float s_scores[TK], s_attn[TK], s_cov[TK];
    int tid = threadIdx.x, wm = tid>>5, lane = tid&31;

    if (blockIdx.x >= NVBLK){
        int idx = blockIdx.x - NVBLK;
        int u = idx >> 5, b = idx & 31;
        if (u == g_sel[b]) return;   // done by k_tatt_sel
        tatt_tile(tok, tmask, tcov, ta_wc, ta_v, o_ntc, o_tattn,
                  (float*)smraw, s_scores, s_attn, s_cov, u, b, false);
        return;
    }

    // ------- vocab GEMM path -------
    float* sW = (float*)smraw;
    int g = lane>>2, tg = lane&3;
    long v0 = (long)blockIdx.x * 128;

    int idx0 = lane*2, idx1 = lane*2+1;
    int row0 = idx0>>2, c40 = idx0&3;
    int row1 = idx1>>2, c41 = idx1&3;
    long gv0 = v0 + wm*16 + row0; if (gv0 >= V) gv0 = V-1;
    long gv1 = v0 + wm*16 + row1; if (gv1 >= V) gv1 = V-1;
    const float* src0 = W2 + gv0*D + c40*4;
    const float* src1 = W2 + gv1*D + c41*4;
    float* wbase = sW + wm*WNST*WSTGF;
    unsigned sb = smem_u32(wbase);
    unsigned dst0 = sb + (unsigned)(row0*64 + ((c40 ^ (row0&3))*16));
    unsigned dst1 = sb + (unsigned)(row1*64 + ((c41 ^ (row1&3))*16));

    #pragma unroll
    for (int s=0; s<4; s++){
        CPA(dst0 + (unsigned)s*1024u, src0 + s*16);
        CPA(dst1 + (unsigned)s*1024u, src1 + s*16);
        CPC();
    }

    float dd[4][4];
    #pragma unroll
    for (int nt=0;nt<4;nt++){ dd[nt][0]=dd[nt][1]=dd[nt][2]=dd[nt][3]=0.f; }

    int r3 = g & 3;
    int o_lo = ((tg>>1) ^ r3)*4 + (tg&1)*2;
    int o_hi = (((tg>>1)|2) ^ r3)*4 + (tg&1)*2;
    int rA = g*16, rB = (g+8)*16;
    const uint4* hp = g_hp + (long)g*128 + tg;

    for (int kc=0; kc<32; kc++){
        CPW3();
        if (kc+4 < 32){
            unsigned st = (unsigned)((kc+4)%WNST)*1024u;
            CPA(dst0 + st, src0 + (kc+4)*16);
            CPA(dst1 + st, src1 + (kc+4)*16);
        }
        CPC();

        const float* sw = wbase + (kc%WNST)*WSTGF;
        float2 fa0 = *(const float2*)(sw + rA + o_lo);
        float2 fa1 = *(const float2*)(sw + rB + o_lo);
        float2 fa2 = *(const float2*)(sw + rA + o_hi);
        float2 fa3 = *(const float2*)(sw + rB + o_hi);

        unsigned ah0,al0,ah1,al1,ah2,al2,ah3,al3;
        cvt_hilo(fa0, ah0, al0);
        cvt_hilo(fa1, ah1, al1);
        cvt_hilo(fa2, ah2, al2);
        cvt_hilo(fa3, ah3, al3);

        const uint4* hpk = hp + kc*4;
        #pragma unroll
        for (int nt=0; nt<4; nt++){
            uint4 bc = hpk[(long)nt*1024];
            mma16816(dd[nt], ah0, ah1, ah2, ah3, bc.x, bc.z);  // hi*hi
            mma16816(dd[nt], al0, al1, al2, al3, bc.x, bc.z);  // lo*hi
            mma16816(dd[nt], ah0, ah1, ah2, ah3, bc.y, bc.w);  // hi*lo
        }
    }

    long rr0 = v0 + wm*16 + g;
    long rr1 = rr0 + 8;
    bool ok0 = (rr0 < V), ok1 = (rr1 < V);
    float bias0 = ok0 ? b2[rr0] : 0.f;
    float bias1 = ok1 ? b2[rr1] : 0.f;
    #pragma unroll
    for (int nt=0; nt<4; nt++){
        int n = nt*8 + tg*2;
        if (ok0){
            g_logits[(long)n*V + rr0]     = dd[nt][0] + bias0;
            g_logits[(long)(n+1)*V + rr0] = dd[nt][1] + bias0;
        }
        if (ok1){
            g_logits[(long)n*V + rr1]     = dd[nt][2] + bias1;
            g_logits[(long)(n+1)*V + rr1] = dd[nt][3] + bias1;
        }
    }

    // fused partial softmax stats
    #pragma unroll
    for (int nt=0; nt<4; nt++){
        #pragma unroll
        for (int p=0; p<2; p++){
            float x0 = ok0 ? dd[nt][p]   + bias0 : -1e30f;
            float x1 = ok1 ? dd[nt][p+2] + bias1 : -1e30f;
            float m = fmaxf(x0, x1);
            #pragma unroll
            for (int o=4; o<32; o<<=1) m = fmaxf(m, __shfl_xor_sync(0xffffffffu, m, o));
            float s = (ok0 ? expf(x0 - m) : 0.f) + (ok1 ? expf(x1 - m) : 0.f);
            #pragma unroll
            for (int o=4; o<32; o<<=1) s += __shfl_xor_sync(0xffffffffu, s, o);
            if (g == 0){
                int n = nt*8 + tg*2 + p;
                sm_m[wm][n] = m;
                sm_s[wm][n] = s;
            }
        }
    }
    __syncthreads();
    if (wm == 0){
        float M = -1e30f;
        #pragma unroll
        for (int w=0; w<8; w++) M = fmaxf(M, sm_m[w][lane]);
        float S = 0.f;
        #pragma unroll
        for (int w=0; w<8; w++) S += sm_s[w][lane] * expf(sm_m[w][lane] - M);
        g_pm[(long)lane*512 + blockIdx.x] = M;
        g_ps[(long)lane*512 + blockIdx.x] = S;
    }
}

// ---------------- K7: combine partial stats (tiny) ----------------
__global__ void k_red(){
    int b = blockIdx.x, tid = threadIdx.x;
    __shared__ float smm[256], sms[256];
    float m0 = (tid      < NVBLK) ? g_pm[(long)b*512 + tid]       : -1e30f;
    float s0 = (tid      < NVBLK) ? g_ps[(long)b*512 + tid]       : 0.f;
    float m1 = (tid+256  < NVBLK) ? g_pm[(long)b*512 + tid + 256] : -1e30f;
    float s1 = (tid+256  < NVBLK) ? g_ps[(long)b*512 + tid + 256] : 0.f;
    float m = fmaxf(m0, m1);
    smm[tid] = m;
    __syncthreads();
    for (int o=128;o;o>>=1){ if (tid<o) smm[tid]=fmaxf(smm[tid],smm[tid+o]); __syncthreads(); }
    float M = smm[0];
    __syncthreads();
    float s = s0*expf(m0 - M) + s1*expf(m1 - M);
    sms[tid] = s;
    __syncthreads();
    for (int o=128;o;o>>=1){ if (tid<o) sms[tid]+=sms[tid+o]; __syncthreads(); }
    if (!tid){ g_m[b] = M; g_inv_s[b] = 1.f/sms[0]; }
}

// ---------------- K8: vocab_dist ----------------
__global__ void k_soft(float* __restrict__ o_vocab){
    long i = (long)blockIdx.x*256 + threadIdx.x;
    if (i >= (long)B*V) return;
    int b = (int)(i / V);
    o_vocab[i] = expf(g_logits[i] - g_m[b]) * g_inv_s[b];
}

// ---------------- launch ----------------
extern "C" void kernel_launch(void* const* d_in, const int* in_sizes, int n_in,
                              void* d_out, int out_size){
    const float* tf    = (const float*)d_in[0];
    const float* enc   = (const float*)d_in[2];
    const float* umask = (const float*)d_in[3];
    const float* tok   = (const float*)d_in[4];
    const float* tmask = (const float*)d_in[5];
    const float* cov   = (const float*)d_in[6];
    const float* tcov  = (const float*)d_in[7];
    const float* ua_Wp = (const float*)d_in[8];
    const float* ua_bp = (const float*)d_in[9];
    const float* ua_v  = (const float*)d_in[10];
    const float* ua_wc = (const float*)d_in[11];
    const float* ta_Wp = (const float*)d_in[12];
    const float* ta_bp = (const float*)d_in[13];
    const float* ta_v  = (const float*)d_in[14];
    const float* ta_wc = (const float*)d_in[15];
    const float* pgen_W= (const float*)d_in[16];
    const float* pgen_b= (const float*)d_in[17];
    const float* W1    = (const float*)d_in[18];
    const float* b1    = (const float*)d_in[19];
    const float* W2    = (const float*)d_in[20];
    const float* b2    = (const float*)d_in[21];
    const float* ln_g  = (const float*)d_in[22];
    const float* ln_b  = (const float*)d_in[23];

    float* out = (float*)d_out;
    float* o_vocab = out;
    float* o_tattn = o_vocab + (long)B*V;
    float* o_pgen  = o_tattn + B*TK;
    float* o_ucov  = o_pgen + B;
    float* o_ntc   = o_ucov + B*U;
    float* o_uidx  = o_ntc + (long)U*B*TK;

    cudaFuncSetAttribute(k_tatt_sel, cudaFuncAttributeMaxDynamicSharedMemorySize, SEL_SMEM);
    cudaFuncSetAttribute(k_main, cudaFuncAttributeMaxDynamicSharedMemorySize, MAIN_SMEM);

    k_ln   <<<B, 256>>>(tf, ln_g, ln_b);
    k_proj <<<dim3(D/8, B/8, 2), 256>>>(ua_Wp, ua_bp, ta_Wp, ta_bp);
    k_uatt <<<B, 256>>>(enc, umask, cov, ua_wc, ua_v, pgen_W, pgen_b,
                        o_ucov, o_pgen, o_uidx);
    k_tatt_sel <<<B, 256, SEL_SMEM>>>(tok, tmask, tcov, ta_wc, ta_v, o_ntc, o_tattn);
    k_h    <<<dim3(D/8, B/8), 256>>>(W1, b1);
    k_pack <<<16, 256>>>();
    k_main <<<NVBLK + U*B, 256, MAIN_SMEM>>>(W2, b2, tok, tmask, tcov, ta_wc, ta_v,
                                             o_ntc, o_tattn);
    k_red  <<<B, 256>>>();
    k_soft <<<(int)(((long)B*V + 255)/256), 256>>>(o_vocab);
}